// round 12
// baseline (speedup 1.0000x reference)
#include <cuda_runtime.h>
#include <cstddef>

// ---------------------------------------------------------------------------
// Fused gConv3d, o-split for 2 CTAs/SM:
//   CTA = (spatial, o-half). 3456 blocks, 640 threads, min 2 blocks/SM.
//   q[obL,h,w]       = sum_{c,f} w[oG,c,f,b] * x[c, xi+fi, yi+fj, zi+fk, h, w]
//   acc[g,oL,hc,wc]  = sum_{b,u,v} basis[g,b,u,v] * q[oL*7+b, hc+u, wc+v]
//   out[g*8+oG,...]  = acc[gg, oL, ii, jj] + biassum[gg*8+oG] ; border -> 0
//   gg = border(h,w) ? (g+1)%12 : g ; ii = clip(h,1,6)-1 ; jj = clip(w,1,38)-1
// ---------------------------------------------------------------------------

typedef unsigned long long u64;

__device__ __forceinline__ u64 ffma2(u64 a, u64 b, u64 c) {
    u64 d;
    asm("fma.rn.f32x2 %0,%1,%2,%3;" : "=l"(d) : "l"(a), "l"(b), "l"(c));
    return d;
}
__device__ __forceinline__ u64 pack2(float lo, float hi) {
    u64 d;
    asm("mov.b64 %0,{%1,%2};" : "=l"(d) : "f"(lo), "f"(hi));
    return d;
}
__device__ __forceinline__ void unpack2(u64 v, float& lo, float& hi) {
    asm("mov.b64 {%0,%1},%2;" : "=f"(lo), "=f"(hi) : "l"(v));
}

// SMEM layout (floats):
//   sq   [28][8][50] = 11200   (row = oL*7+b, stride 400; h pitch 50)
//   union @11200: sw[6912] (stage-1 weights) | sacc[48][240] = 11520
//   sbp  756 @22720  (basis paired (g0,g1) interleaved, u64-aligned)
//   sbiasv 96 @23476
#define SQ_OFF     0
#define SW_OFF     11200
#define SACC_OFF   11200
#define SBP_OFF    22720
#define SBIAS_OFF  23476
#define SMEM_FLOATS 23572
#define SMEM_BYTES  (SMEM_FLOATS * 4)

__global__ __launch_bounds__(640, 2) void k_fused(const float* __restrict__ x,
                                                  const float* __restrict__ wgt,
                                                  const float* __restrict__ bias,
                                                  const float* __restrict__ basis,
                                                  const int* __restrict__ bbg,
                                                  float* __restrict__ out) {
    extern __shared__ float smem[];
    float* sq     = smem + SQ_OFF;
    float* sw     = smem + SW_OFF;
    float* sacc   = smem + SACC_OFF;
    float* sbp    = smem + SBP_OFF;
    float* sbiasv = smem + SBIAS_OFF;

    const int bxs = (int)blockIdx.x >> 1;       // spatial index 0..1727
    const int ho  = (int)blockIdx.x & 1;        // o-half: oG = ho*4 + oL
    const int z   = bxs % 12, y = (bxs / 12) % 12, xx = bxs / 144;
    const int tid = threadIdx.x;

    const bool borderblk = (xx < 1) | (xx > 9) | (y < 1) | (y > 9) | (z < 1) | (z > 9);
    if (borderblk) {
        const float4 zv = make_float4(0.f, 0.f, 0.f, 0.f);
        float4* ob4 = (float4*)out;
        for (int e = tid; e < 48 * 80; e += 640) {
            const int goL = e / 80, k = e - goL * 80;
            const int g = goL >> 2, oL = goL & 3;
            const int go = g * 8 + ho * 4 + oL;
            ob4[(size_t)go * 138240 + (size_t)bxs * 80 + k] = zv;
        }
        return;
    }

    // ---- Phase 0: stage weights (this half), paired basis, biassums ---------
    // sw[(c*27+f)*32 + oL*8 + slot], slot: b0..b6,b6dup
    for (int idx = tid; idx < 6912; idx += 640) {
        const int slot = idx & 7;
        const int oL   = (idx >> 3) & 3;
        const int cf   = idx >> 5;
        const int b    = (slot == 7) ? 6 : slot;
        const int oG   = ho * 4 + oL;
        const int c = cf / 27, f = cf - c * 27;
        sw[idx] = wgt[((oG * 8 + c) * 27 + f) * 7 + b];
    }
    for (int i = tid; i < 378; i += 640) {
        const int gp = i / 63, r = i - gp * 63;
        ((float2*)sbp)[i] = make_float2(basis[gp * 126 + r],
                                        basis[gp * 126 + 63 + r]);
    }
    if (tid >= 512 && tid < 608) {
        const int t2 = tid - 512;
        const int b  = bbg[t2];
        float s = 0.f;
        for (int k = 0; k < 27; k++) s += bias[b * 27 + k];
        sbiasv[t2] = s;
    }
    __syncthreads();

    // ---- Stage 1: 2 hw x 7 b (one oL) per thread ----------------------------
    const int xi = xx - 1, yi = y - 1, zi = z - 1;
    const int hw0 = (tid % 160) * 2;
    const int oL  = tid / 160;                  // warp-uniform 0..3

    u64 acc2[7];
#pragma unroll
    for (int i = 0; i < 7; i++) acc2[i] = 0ull;

#pragma unroll 1
    for (int c = 0; c < 8; c++) {
        const float* xpc = x + (size_t)(((c * 12 + xi) * 12 + yi) * 12 + zi) * 320 + hw0;
        const float* wpc = sw + c * 864 + oL * 8;          // 27*32 = 864
#pragma unroll
        for (int fi = 0; fi < 3; fi++) {
#pragma unroll
            for (int fj = 0; fj < 3; fj++) {
                const float* xq = xpc + (fi * 144 + fj * 12) * 320;
                const float* wq = wpc + (fi * 9 + fj * 3) * 32;
#pragma unroll
                for (int fk = 0; fk < 3; fk++) {
                    const float2 xv = *(const float2*)(xq + fk * 320);
                    const u64 x00 = pack2(xv.x, xv.x);
                    const u64 x11 = pack2(xv.y, xv.y);
                    const u64 xp  = pack2(xv.x, xv.y);
                    const ulonglong2 wA = *(const ulonglong2*)(wq + fk * 32);      // (b0,b1),(b2,b3)
                    const ulonglong2 wB = *(const ulonglong2*)(wq + fk * 32 + 4);  // (b4,b5),(b6,b6)
                    acc2[0] = ffma2(wA.x, x00, acc2[0]);
                    acc2[1] = ffma2(wA.x, x11, acc2[1]);
                    acc2[2] = ffma2(wA.y, x00, acc2[2]);
                    acc2[3] = ffma2(wA.y, x11, acc2[3]);
                    acc2[4] = ffma2(wB.x, x00, acc2[4]);
                    acc2[5] = ffma2(wB.x, x11, acc2[5]);
                    acc2[6] = ffma2(wB.y, xp,  acc2[6]);
                }
            }
        }
    }

    // store q tile: sq[(oL*7+b)*400 + h*50 + w]
    {
        const int h = hw0 / 40, w = hw0 - h * 40;   // hw0 even -> same h, w even
        float* qb = sq + oL * 2800 + h * 50 + w;
#pragma unroll
        for (int bp = 0; bp < 3; bp++) {
            float l0, h0, l1, h1;
            unpack2(acc2[2 * bp],     l0, h0);   // (b2bp, b2bp+1) @ hw0
            unpack2(acc2[2 * bp + 1], l1, h1);   // same @ hw0+1
            *(float2*)(qb + (2 * bp) * 400)     = make_float2(l0, l1);
            *(float2*)(qb + (2 * bp + 1) * 400) = make_float2(h0, h1);
        }
        float b6a, b6b;
        unpack2(acc2[6], b6a, b6b);              // b6 @ (hw0, hw0+1)
        *(float2*)(qb + 6 * 400) = make_float2(b6a, b6b);
    }
    __syncthreads();   // sw dead; sacc live

    // ---- Phase B: g-paired, width-6 chunks, 2 rounds ------------------------
    // half-task ht: task = ht>>1 (gp*4+oL2), round = ht&1
    // lane: hcx = lane>>2 (clamp 5), ch = lane&3 ; wc0 = round*24 + ch*6
    const int warpId = tid >> 5, lane = tid & 31;
    const int hcx   = lane >> 2;
    const int ch    = lane & 3;
    const int hc    = (hcx < 6) ? hcx : 5;

#pragma unroll 1
    for (int ht = warpId; ht < 48; ht += 20) {
        const int round = ht & 1;
        const int task  = ht >> 1;
        const int gp  = task >> 2;               // 0..5
        const int oL2 = task & 3;                // 0..3
        const int wc0 = round * 24 + ch * 6;     // 0,6,12,18 | 24,30,36,42
        const int width = (wc0 <= 32) ? 6 : (wc0 == 36 ? 2 : 0);

        u64 accv[6];
#pragma unroll
        for (int i = 0; i < 6; i++) accv[i] = 0ull;

        const u64* bpb = (const u64*)(sbp) + gp * 63;
        const int qoff = wc0 < 44 ? wc0 : 36;    // keep loads in-row for idle lanes
#pragma unroll 1
        for (int b = 0; b < 7; b++) {
            const float* qbase = sq + (oL2 * 7 + b) * 400 + qoff;
#pragma unroll
            for (int u = 0; u < 3; u++) {
                const float* qr = qbase + (hc + u) * 50;
                // aligned u64 loads covering wc0..wc0+7
                u64 A0 = *(const u64*)(qr);
                u64 A1 = *(const u64*)(qr + 2);
                u64 A2 = *(const u64*)(qr + 4);
                u64 A3 = *(const u64*)(qr + 6);
                float f0, f1, f2, f3, f4, f5, f6, f7;
                unpack2(A0, f0, f1); unpack2(A1, f2, f3);
                unpack2(A2, f4, f5); unpack2(A3, f6, f7);
                const u64 s0 = pack2(f0, f0), s1 = pack2(f1, f1);
                const u64 s2 = pack2(f2, f2), s3 = pack2(f3, f3);
                const u64 s4 = pack2(f4, f4), s5 = pack2(f5, f5);
                const u64 s6 = pack2(f6, f6), s7 = pack2(f7, f7);
                const u64 c0 = bpb[b * 9 + u * 3 + 0];
                const u64 c1 = bpb[b * 9 + u * 3 + 1];
                const u64 c2 = bpb[b * 9 + u * 3 + 2];
                accv[0] = ffma2(c0, s0, ffma2(c1, s1, ffma2(c2, s2, accv[0])));
                accv[1] = ffma2(c0, s1, ffma2(c1, s2, ffma2(c2, s3, accv[1])));
                accv[2] = ffma2(c0, s2, ffma2(c1, s3, ffma2(c2, s4, accv[2])));
                accv[3] = ffma2(c0, s3, ffma2(c1, s4, ffma2(c2, s5, accv[3])));
                accv[4] = ffma2(c0, s4, ffma2(c1, s5, ffma2(c2, s6, accv[4])));
                accv[5] = ffma2(c0, s5, ffma2(c1, s6, ffma2(c2, s7, accv[5])));
            }
        }
        // stores: sacc[(g*4+oL)*240 + hc*40 + wc], g0 = 2*gp, g1 = 2*gp+1
        if (hcx < 6 && width > 0) {
            float* r0 = sacc + ((2 * gp) * 4 + oL2) * 240 + hc * 40 + wc0;
            float* r1 = r0 + 4 * 240;
            float lo0, hi0, lo1, hi1;
#pragma unroll
            for (int i = 0; i < 6; i += 2) {
                if (i < width) {
                    unpack2(accv[i],     lo0, hi0);
                    unpack2(accv[i + 1], lo1, hi1);
                    *(float2*)(r0 + i) = make_float2(lo0, lo1);
                    *(float2*)(r1 + i) = make_float2(hi0, hi1);
                }
            }
        }
    }
    __syncthreads();

    // ---- Phase C: analytic gather, add bias, write out ----------------------
    {
        const int hw   = tid % 320;
        const int half = tid / 320;
        const int h = hw / 40, w = hw - h * 40;
        const bool bord = (h == 0) | (h == 7) | (w == 0) | (w == 39);
        const int ii = min(max(h, 1), 6) - 1;
        const int jj = min(max(w, 1), 38) - 1;
        const int pix = ii * 40 + jj;
        const size_t obase = (size_t)bxs * 320 + hw;
#pragma unroll 1
        for (int goL = half; goL < 48; goL += 2) {
            const int g = goL >> 2, oL2 = goL & 3;
            int gg = g;
            if (bord) { gg = g + 1; if (gg == 12) gg = 0; }
            const float v = sacc[(gg * 4 + oL2) * 240 + pix]
                          + sbiasv[gg * 8 + ho * 4 + oL2];
            const int go = g * 8 + ho * 4 + oL2;
            out[(size_t)go * 552960 + obase] = v;
        }
    }
}

// ---------------------------------------------------------------------------
extern "C" void kernel_launch(void* const* d_in, const int* in_sizes, int n_in,
                              void* d_out, int out_size) {
    const float* x     = (const float*)d_in[0];
    const float* wgt   = (const float*)d_in[1];
    const float* bias  = (const float*)d_in[2];
    const float* basis = (const float*)d_in[3];
    const int*   bbg   = (const int*)d_in[7];
    float* out = (float*)d_out;

    cudaFuncSetAttribute(k_fused, cudaFuncAttributeMaxDynamicSharedMemorySize,
                         SMEM_BYTES);

    k_fused<<<3456, 640, SMEM_BYTES>>>(x, wgt, bias, basis, bbg, out);
}

// round 13
// speedup vs baseline: 1.3006x; 1.3006x over previous
#include <cuda_runtime.h>
#include <cstddef>

// ---------------------------------------------------------------------------
// Fused gConv3d, f32x2-packed, phase-B g-quad grouping:
//   q[ob,h,w]      = sum_{c,f} wT[c,f,ob] * x[c, xi+fi, yi+fj, zi+fk, h, w]
//   acc[g,o,hc,wc] = sum_{b,u,v} basis[g,b,u,v] * q[o*7+b, hc+u, wc+v]
//   out[go,x,y,z,h,w] = acc[gg, o, ii, jj] + biassum ;  border blocks -> 0
//   gg = border(h,w) ? (g+1)%12 : g ; ii = clip(h,1,6)-1 ; jj = clip(w,1,38)-1
// 1728 blocks (one per (x,y,z)), 640 threads.
// ---------------------------------------------------------------------------

typedef unsigned long long u64;

__device__ __forceinline__ u64 ffma2(u64 a, u64 b, u64 c) {
    u64 d;
    asm("fma.rn.f32x2 %0,%1,%2,%3;" : "=l"(d) : "l"(a), "l"(b), "l"(c));
    return d;
}
__device__ __forceinline__ u64 pack2(float lo, float hi) {
    u64 d;
    asm("mov.b64 %0,{%1,%2};" : "=l"(d) : "f"(lo), "f"(hi));
    return d;
}
__device__ __forceinline__ void unpack2(u64 v, float& lo, float& hi) {
    asm("mov.b64 {%0,%1},%2;" : "=f"(lo), "=f"(hi) : "l"(v));
}

// SMEM layout (floats):
//   sq   [56][8][50] = 22400   (row pitch 50, ob stride 400)
//   union @22400: sw[13824] (stage-1 weights) | sacc[96][234] = 22464
//   sbp  756 (basis pre-paired (g0,g1) interleaved)
//   sbiasv 96
#define SQ_OFF     0
#define SW_OFF     22400
#define SACC_OFF   22400
#define SBP_OFF    44864
#define SBIAS_OFF  45620
#define SMEM_FLOATS 45716
#define SMEM_BYTES  (SMEM_FLOATS * 4)

__global__ __launch_bounds__(640) void k_fused(const float* __restrict__ x,
                                               const float* __restrict__ wgt,
                                               const float* __restrict__ bias,
                                               const float* __restrict__ basis,
                                               const int* __restrict__ bbg,
                                               float* __restrict__ out) {
    extern __shared__ float smem[];
    float* sq     = smem + SQ_OFF;
    float* sw     = smem + SW_OFF;
    float* sacc   = smem + SACC_OFF;
    float* sbp    = smem + SBP_OFF;
    float* sbiasv = smem + SBIAS_OFF;

    const int bx  = blockIdx.x;
    const int z   = bx % 12, y = (bx / 12) % 12, xx = bx / 144;
    const int tid = threadIdx.x;

    const bool borderblk = (xx < 1) | (xx > 9) | (y < 1) | (y > 9) | (z < 1) | (z > 9);
    if (borderblk) {
        const float4 zv = make_float4(0.f, 0.f, 0.f, 0.f);
        float4* ob4 = (float4*)out;
        for (int e = tid; e < 96 * 80; e += 640) {
            const int go = e / 80, k = e - go * 80;
            ob4[(size_t)go * 138240 + (size_t)bx * 80 + k] = zv;
        }
        return;
    }

    // ---- Phase 0: stage weights (transposed+padded), paired basis, biassums --
    for (int idx = tid; idx < 13824; idx += 640) {
        const int cf  = idx >> 6;
        const int rem = idx & 63;
        const int obg = rem >> 4, j = rem & 15;
        float v = 0.f;
        if (j < 14) {
            const int ob = obg * 14 + j;
            const int o = ob / 7, b = ob - o * 7;
            const int c = cf / 27, f = cf - c * 27;
            v = wgt[((o * 8 + c) * 27 + f) * 7 + b];
        }
        sw[idx] = v;
    }
    for (int i = tid; i < 378; i += 640) {
        const int gp = i / 63, r = i - gp * 63;
        sbp[2 * i]     = basis[gp * 126 + r];        // g = 2*gp
        sbp[2 * i + 1] = basis[gp * 126 + 63 + r];   // g = 2*gp+1
    }
    if (tid >= 512 && tid < 608) {
        const int t2 = tid - 512;
        const int b  = bbg[t2];
        float s = 0.f;
        for (int k = 0; k < 27; k++) s += bias[b * 27 + k];
        sbiasv[t2] = s;
    }
    __syncthreads();

    // ---- Stage 1: 2 hw x 14 ob per thread, FFMA2 over ob-pairs --------------
    const int xi = xx - 1, yi = y - 1, zi = z - 1;
    const int hw0 = (tid % 160) * 2;
    const int obg = tid / 160;                 // 0..3 (warp-uniform)
    const int ob0 = obg * 14;

    u64 acc2[14];
#pragma unroll
    for (int i = 0; i < 14; i++) acc2[i] = 0ull;

#pragma unroll 1
    for (int c = 0; c < 8; c++) {
        const float* xpc = x + (size_t)(((c * 12 + xi) * 12 + yi) * 12 + zi) * 320 + hw0;
        const float* wpc = sw + c * 1728 + obg * 16;
#pragma unroll
        for (int fi = 0; fi < 3; fi++) {
#pragma unroll
            for (int fj = 0; fj < 3; fj++) {
                const float* xq = xpc + (fi * 144 + fj * 12) * 320;
                const float* wq = wpc + (fi * 9 + fj * 3) * 64;
#pragma unroll
                for (int fk = 0; fk < 3; fk++) {
                    const float2 xv = *(const float2*)(xq + fk * 320);
                    const u64 x0 = pack2(xv.x, xv.x);
                    const u64 x1 = pack2(xv.y, xv.y);
                    const ulonglong2* wv = (const ulonglong2*)(wq + fk * 64);
                    const ulonglong2 wa  = wv[0];
                    const ulonglong2 wb  = wv[1];
                    const ulonglong2 wcp = wv[2];
                    const ulonglong2 wd  = wv[3];
                    acc2[0]  = ffma2(wa.x, x0, acc2[0]);
                    acc2[1]  = ffma2(wa.x, x1, acc2[1]);
                    acc2[2]  = ffma2(wa.y, x0, acc2[2]);
                    acc2[3]  = ffma2(wa.y, x1, acc2[3]);
                    acc2[4]  = ffma2(wb.x, x0, acc2[4]);
                    acc2[5]  = ffma2(wb.x, x1, acc2[5]);
                    acc2[6]  = ffma2(wb.y, x0, acc2[6]);
                    acc2[7]  = ffma2(wb.y, x1, acc2[7]);
                    acc2[8]  = ffma2(wcp.x, x0, acc2[8]);
                    acc2[9]  = ffma2(wcp.x, x1, acc2[9]);
                    acc2[10] = ffma2(wcp.y, x0, acc2[10]);
                    acc2[11] = ffma2(wcp.y, x1, acc2[11]);
                    acc2[12] = ffma2(wd.x, x0, acc2[12]);
                    acc2[13] = ffma2(wd.x, x1, acc2[13]);
                }
            }
        }
    }

    // store q tile: sq[ob*400 + h*50 + w]
    {
        const int h = hw0 / 40, w = hw0 - h * 40;   // hw0 even -> same h
        float* qb = sq + h * 50 + w;
#pragma unroll
        for (int p = 0; p < 7; p++) {
            float a0, a1, b0v, b1v;
            unpack2(acc2[2 * p],     a0, a1);   // (ob0+2p, ob0+2p+1) @ hw0
            unpack2(acc2[2 * p + 1], b0v, b1v); // same obs @ hw0+1
            float* r0 = qb + (ob0 + 2 * p) * 400;
            float* r1 = qb + (ob0 + 2 * p + 1) * 400;
            r0[0] = a0; r0[1] = b0v;
            r1[0] = a1; r1[1] = b1v;
        }
    }
    __syncthreads();   // sw dead; sacc (aliased) live

    // ---- Phase B: g-QUAD tasks. warp = (gq, o); lane = (hc, chunk) ----------
    // 24 tasks: gq in 0..2 covers g in {4gq..4gq+3} via 2 basis-pairs;
    // q loaded once per (b,u), consumed by both accumulator sets.
    const int warpId = tid >> 5, lane = tid & 31;
    const int hcx   = lane >> 2;
    const int chunk = lane & 3;
    const int hc    = (hcx < 6) ? hcx : 5;     // idle lanes -> broadcast dup
    const int wc0   = chunk * 10;

#pragma unroll 1
    for (int wt = warpId; wt < 24; wt += 20) {
        const int gq = wt >> 3;                // 0..2
        const int o  = wt & 7;

        u64 accv0[10], accv1[10];
#pragma unroll
        for (int i = 0; i < 10; i++) { accv0[i] = 0ull; accv1[i] = 0ull; }

        const u64* bp0 = (const u64*)(sbp) + (2 * gq) * 63;   // g 4gq,4gq+1
        const u64* bp1 = bp0 + 63;                            // g 4gq+2,4gq+3
#pragma unroll 1
        for (int b = 0; b < 7; b++) {
            const float* qbase = sq + (o * 7 + b) * 400 + wc0;
#pragma unroll
            for (int u = 0; u < 3; u++) {
                const float* qr = qbase + (hc + u) * 50;
                u64 qp[12];
#pragma unroll
                for (int k = 0; k < 6; k++) {
                    const float2 qv = *(const float2*)(qr + 2 * k);
                    qp[2 * k]     = pack2(qv.x, qv.x);
                    qp[2 * k + 1] = pack2(qv.y, qv.y);
                }
                const int bo = b * 9 + u * 3;
                const u64 c00 = bp0[bo], c01 = bp0[bo + 1], c02 = bp0[bo + 2];
                const u64 c10 = bp1[bo], c11 = bp1[bo + 1], c12 = bp1[bo + 2];
#pragma unroll
                for (int i = 0; i < 10; i++) {
                    accv0[i] = ffma2(c00, qp[i],
                               ffma2(c01, qp[i + 1],
                               ffma2(c02, qp[i + 2], accv0[i])));
                    accv1[i] = ffma2(c10, qp[i],
                               ffma2(c11, qp[i + 1],
                               ffma2(c12, qp[i + 2], accv1[i])));
                }
            }
        }
        if (hcx < 6) {
            const int width = (chunk < 3) ? 10 : 8;
            // sacc rows: idx = g*8+o, g = 4gq + {0,1,2,3}
            float* r0 = sacc + ((4 * gq) * 8 + o) * 234 + hc * 39 + wc0;
            float* r1 = r0 + 8 * 234;
            float* r2 = r0 + 16 * 234;
            float* r3 = r0 + 24 * 234;
#pragma unroll
            for (int i = 0; i < 10; i++) {
                if (i < width) {
                    float v0, v1, v2, v3;
                    unpack2(accv0[i], v0, v1);
                    unpack2(accv1[i], v2, v3);
                    r0[i] = v0;
                    r1[i] = v1;
                    r2[i] = v2;
                    r3[i] = v3;
                }
            }
        }
    }
    __syncthreads();

    // ---- Phase C: analytic gather, add bias, write out ----------------------
    {
        const int hw   = tid % 320;
        const int half = tid / 320;
        const int h = hw / 40, w = hw - h * 40;
        const bool bord = (h == 0) | (h == 7) | (w == 0) | (w == 39);
        const int ii = min(max(h, 1), 6) - 1;
        const int jj = min(max(w, 1), 38) - 1;
        const int pix = ii * 39 + jj;
        const size_t obase = (size_t)bx * 320 + hw;
#pragma unroll 1
        for (int go = half; go < 96; go += 2) {
            const int g = go >> 3, o = go & 7;
            int gg = g;
            if (bord) { gg = g + 1; if (gg == 12) gg = 0; }
            const int idx = gg * 8 + o;
            const float v = sacc[idx * 234 + pix] + sbiasv[idx];
            out[(size_t)go * 552960 + obase] = v;
        }
    }
}

// ---------------------------------------------------------------------------
extern "C" void kernel_launch(void* const* d_in, const int* in_sizes, int n_in,
                              void* d_out, int out_size) {
    const float* x     = (const float*)d_in[0];
    const float* wgt   = (const float*)d_in[1];
    const float* bias  = (const float*)d_in[2];
    const float* basis = (const float*)d_in[3];
    const int*   bbg   = (const int*)d_in[7];
    float* out = (float*)d_out;

    cudaFuncSetAttribute(k_fused, cudaFuncAttributeMaxDynamicSharedMemorySize,
                         SMEM_BYTES);

    k_fused<<<1728, 640, SMEM_BYTES>>>(x, wgt, bias, basis, bbg, out);
}